// round 1
// baseline (speedup 1.0000x reference)
#include <cuda_runtime.h>
#include <cstdint>

// Problem constants (fixed by the reference):
//   x: [B, C, L, L] fp32, B=128, C=3, L=256, N=4 boxes per sample
//   X/Y/W/H: [N, B] int32
// out[b,c,y,x] = inside-any-box(b,y,x) ? 0 : x[b,c,y,x]
// Mask depends on (b, y, x) only — shared across channels.

#define BB 128
#define CC 3
#define LL 256
#define NN 4

// Total float4 elements: B*C*L*L/4 = 6,291,456
#define TOTAL4 (BB * CC * LL * LL / 4)

__global__ __launch_bounds__(256)
void masking_kernel(const float4* __restrict__ x4,
                    const int* __restrict__ Xb,
                    const int* __restrict__ Yb,
                    const int* __restrict__ Wb,
                    const int* __restrict__ Hb,
                    float4* __restrict__ out4)
{
    int i4 = blockIdx.x * blockDim.x + threadIdx.x;
    if (i4 >= TOTAL4) return;

    int base = i4 << 2;              // flat float index
    int col  = base & (LL - 1);      // column of first of 4 elements
    int y    = (base >> 8) & (LL - 1);
    int b    = base / (CC * LL * LL); // 196608; compiler -> mulhi

    // Load the float4 early so the streaming load overlaps the box-param loads.
    float4 v = x4[i4];

    // Build a 4-bit column mask for cols [col, col+3].
    unsigned m = 0u;
#pragma unroll
    for (int n = 0; n < NN; n++) {
        int xs = __ldg(&Xb[n * BB + b]);
        int ys = __ldg(&Yb[n * BB + b]);
        int w  = __ldg(&Wb[n * BB + b]);
        int h  = __ldg(&Hb[n * BB + b]);
        // row inside [ys, ys+h]?
        bool yin = (y >= ys) && (y <= ys + h);
        if (yin) {
            int xe = xs + w;
#pragma unroll
            for (int j = 0; j < 4; j++) {
                int c = col + j;
                m |= ((c >= xs) & (c <= xe)) ? (1u << j) : 0u;
            }
        }
    }

    if (m & 1u) v.x = 0.0f;
    if (m & 2u) v.y = 0.0f;
    if (m & 4u) v.z = 0.0f;
    if (m & 8u) v.w = 0.0f;

    out4[i4] = v;
}

extern "C" void kernel_launch(void* const* d_in, const int* in_sizes, int n_in,
                              void* d_out, int out_size)
{
    const float4* x4 = (const float4*)d_in[0];
    const int* Xb = (const int*)d_in[1];
    const int* Yb = (const int*)d_in[2];
    const int* Wb = (const int*)d_in[3];
    const int* Hb = (const int*)d_in[4];
    float4* out4 = (float4*)d_out;

    const int threads = 256;
    const int blocks = (TOTAL4 + threads - 1) / threads;  // 24576
    masking_kernel<<<blocks, threads>>>(x4, Xb, Yb, Wb, Hb, out4);
}